// round 11
// baseline (speedup 1.0000x reference)
#include <cuda_runtime.h>
#include <cuda_fp16.h>
#include <cstdint>

// ---------------------------------------------------------------------------
// LinearPatchMerger (GB300, family-safe):
//   prep_w: g_Wh[1024][4096] = fp16( column-permuted W )      (input-indexed)
//   prep_x: g_Xh[32768][4096] = fp16( unfold-permuted image_features )
//   gemm  : out = g_Xh @ g_Wh^T  via mma.m16n8k16.f16 (f32 accum)
//           128 thr/CTA, 128x128 tile, warp tile 64x64, 2 CTAs/SM,
//           A+B fragments double-buffered across k-slices.
// ---------------------------------------------------------------------------

constexpr int K_TOT = 4096;
constexpr int N_TOT = 1024;
constexpr int M_TOT = 32768;

constexpr int KC = 64;               // K halves per stage (128 B rows)
constexpr int NCHUNK = K_TOT / KC;   // 64
constexpr int NSTAGE = 3;
constexpr int THREADS = 128;         // 4 warps, 2x2 of 64x64 warp tiles

constexpr int A_BYTES = 128 * KC * 2;        // 16 KB
constexpr int B_BYTES = 128 * KC * 2;        // 16 KB
constexpr int STAGE   = A_BYTES + B_BYTES;   // 32 KB
constexpr int SMEM_BYTES = NSTAGE * STAGE;   // 96 KB

__device__ __half g_Xh[(size_t)M_TOT * K_TOT];  // 268 MB permuted fp16 A
__device__ __half g_Wh[(size_t)N_TOT * K_TOT];  // 8 MB permuted fp16 W

#define DEV __device__ __forceinline__

DEV uint32_t smem_u32(const void* p) {
    uint32_t a;
    asm("{ .reg .u64 t; cvta.to.shared.u64 t, %1; cvt.u32.u64 %0, t; }"
        : "=r"(a) : "l"(p));
    return a;
}
DEV void cp16(uint32_t dst, const void* src) {
    asm volatile("cp.async.ca.shared.global [%0], [%1], 16;"
                 :: "r"(dst), "l"(src) : "memory");
}
DEV void cp_commit() { asm volatile("cp.async.commit_group;" ::: "memory"); }
template <int N> DEV void cp_wait() {
    asm volatile("cp.async.wait_group %0;" :: "n"(N) : "memory");
}
DEV void ldmx4(uint32_t* r, uint32_t a) {
    asm volatile("ldmatrix.sync.aligned.m8n8.x4.shared.b16 {%0,%1,%2,%3}, [%4];"
                 : "=r"(r[0]), "=r"(r[1]), "=r"(r[2]), "=r"(r[3]) : "r"(a));
}
DEV void mma_f16(float* d, const uint32_t* a, uint32_t b0, uint32_t b1) {
    asm volatile(
        "mma.sync.aligned.m16n8k16.row.col.f32.f16.f16.f32 "
        "{%0,%1,%2,%3}, {%4,%5,%6,%7}, {%8,%9}, {%0,%1,%2,%3};"
        : "+f"(d[0]), "+f"(d[1]), "+f"(d[2]), "+f"(d[3])
        : "r"(a[0]), "r"(a[1]), "r"(a[2]), "r"(a[3]), "r"(b0), "r"(b1));
}
DEV void stg_cs16(void* p, uint32_t x, uint32_t y, uint32_t z, uint32_t w) {
    asm volatile("st.global.cs.v4.b32 [%0], {%1,%2,%3,%4};"
                 :: "l"(p), "r"(x), "r"(y), "r"(z), "r"(w) : "memory");
}

// ---------------------------------------------------------------------------
// prep W (input-indexed, coalesced both sides)
// ---------------------------------------------------------------------------
__global__ void prep_w_kernel(const float* __restrict__ W) {
    int o = blockIdx.x * blockDim.x + threadIdx.x;   // 0 .. 1M-1
    if (o >= N_TOT * K_TOT / 4) return;
    int dout = o >> 10;
    int d    = o & 1023;
    float4 v = ((const float4*)W)[o];
    __half* base = g_Wh + ((size_t)dout << 12) + d;
    base[0]    = __float2half_rn(v.x);
    base[1024] = __float2half_rn(v.y);
    base[2048] = __float2half_rn(v.z);
    base[3072] = __float2half_rn(v.w);
}

// ---------------------------------------------------------------------------
// prep X: g_Xh[n][q*1024+d] = fp16( X[srcrow(n,q)][d] ), streaming 16B stores
// ---------------------------------------------------------------------------
__global__ void prep_x_kernel(const float* __restrict__ X) {
    const int total = M_TOT * (K_TOT / 8);
    int stride = gridDim.x * blockDim.x;
    for (int o = blockIdx.x * blockDim.x + threadIdx.x; o < total; o += stride) {
        int n  = o >> 9;
        int rh = (o & 511) << 3;
        int q  = rh >> 10;
        int d0 = rh & 1023;
        int im = n >> 12, ml = n & 4095;
        int i = ml >> 6, j = ml & 63;
        int src = (im << 14) + (((i << 1) + (q >> 1)) << 7) + (j << 1) + (q & 1);
        const float4* p = (const float4*)(X + ((size_t)src << 10) + d0);
        float4 v0 = p[0], v1 = p[1];
        __half2 h0 = __floats2half2_rn(v0.x, v0.y);
        __half2 h1 = __floats2half2_rn(v0.z, v0.w);
        __half2 h2 = __floats2half2_rn(v1.x, v1.y);
        __half2 h3 = __floats2half2_rn(v1.z, v1.w);
        stg_cs16(g_Xh + ((size_t)o << 3),
                 *(uint32_t*)&h0, *(uint32_t*)&h1,
                 *(uint32_t*)&h2, *(uint32_t*)&h3);
    }
}

// ---------------------------------------------------------------------------
// GEMM: grid (8 n-tiles, 256 m-tiles), 128 threads, warp tile 64x64.
// smem rows = 64 halves (128 B), 16B-chunk swizzle c^(r&7).
// ---------------------------------------------------------------------------
__global__ void __launch_bounds__(THREADS, 2)
merger_gemm_kernel(float* __restrict__ out) {
    extern __shared__ __align__(1024) char sm[];
    const uint32_t sbase = smem_u32(sm);

    const int tid = threadIdx.x;
    const int wid = tid >> 5;
    const int lid = tid & 31;
    const int bx  = blockIdx.x;     // n-tile 0..7
    const int mt  = blockIdx.y;     // m-tile 0..255

    const int warp_m = wid & 1;     // 64-row half
    const int warp_n = wid >> 1;    // 64-col half
    const int g   = lid >> 2;
    const int tig = lid & 3;

    // ---- producer slots: 8 cp16 A + 8 cp16 B per thread per stage ----
    uint32_t stsOff[8];
    const __half *srcA[8], *srcB[8];
    #pragma unroll
    for (int k2 = 0; k2 < 8; k2++) {
        int f = tid + (k2 << 7);             // 0..1023
        int r = f >> 3;                      // row 0..127
        int c = f & 7;                       // 16B chunk
        stsOff[k2] = (uint32_t)(r * 128 + ((c ^ (r & 7)) << 4));
        srcA[k2] = g_Xh + ((size_t)(mt * 128 + r) << 12) + (c << 3);
        srcB[k2] = g_Wh + ((size_t)(bx * 128 + r) << 12) + (c << 3);
    }

    // ---- consumer ldmatrix lane geometry ----
    const int rA  = (lid & 15);
    const int cbA = lid >> 4;
    const int rB  = ((lid >> 4) << 3) + (lid & 7);
    const int cbB = (lid >> 3) & 1;

    uint32_t aRow[4], bRow[4];
    int aR7[4], bR7[4];
    #pragma unroll
    for (int mi = 0; mi < 4; mi++) {
        int row = warp_m * 64 + mi * 16 + rA;
        aRow[mi] = (uint32_t)(row * 128);
        aR7[mi]  = row & 7;
    }
    #pragma unroll
    for (int nj = 0; nj < 4; nj++) {
        int row = warp_n * 64 + nj * 16 + rB;
        bRow[nj] = (uint32_t)(row * 128);
        bR7[nj]  = row & 7;
    }

    float acc[4][8][4];
    #pragma unroll
    for (int mi = 0; mi < 4; mi++)
        #pragma unroll
        for (int ni = 0; ni < 8; ni++)
            #pragma unroll
            for (int r = 0; r < 4; r++) acc[mi][ni][r] = 0.0f;

    auto load_stage = [&](int st, int kc) {
        const uint32_t aS = sbase + st * STAGE;
        const uint32_t bS = aS + A_BYTES;
        #pragma unroll
        for (int k2 = 0; k2 < 8; k2++) cp16(aS + stsOff[k2], srcA[k2] + kc * KC);
        #pragma unroll
        for (int k2 = 0; k2 < 8; k2++) cp16(bS + stsOff[k2], srcB[k2] + kc * KC);
    };

    #pragma unroll
    for (int s = 0; s < NSTAGE - 1; s++) { load_stage(s, s); cp_commit(); }
    int kc_load = NSTAGE - 1;

    for (int kc = 0; kc < NCHUNK; kc++) {
        cp_wait<NSTAGE - 2>();
        __syncthreads();

        if (kc_load < NCHUNK) { load_stage(kc_load % NSTAGE, kc_load); kc_load++; }
        cp_commit();

        const uint32_t aS = sbase + (kc % NSTAGE) * STAGE;
        const uint32_t bS = aS + A_BYTES;

        // ---- A+B fragments double-buffered across the 4 k-slices ----
        uint32_t afr[2][4][4], bfr[2][4][4];
        #pragma unroll
        for (int mi = 0; mi < 4; mi++) {
            int ch = cbA ^ aR7[mi];                       // s = 0
            ldmx4(afr[0][mi], aS + aRow[mi] + (ch << 4));
        }
        #pragma unroll
        for (int nj = 0; nj < 4; nj++) {
            int ch = cbB ^ bR7[nj];                       // s = 0
            ldmx4(bfr[0][nj], bS + bRow[nj] + (ch << 4));
        }

        #pragma unroll
        for (int s = 0; s < 4; s++) {
            const int cur = s & 1;

            if (s < 3) {
                #pragma unroll
                for (int mi = 0; mi < 4; mi++) {
                    int ch = (2 * (s + 1) + cbA) ^ aR7[mi];
                    ldmx4(afr[cur ^ 1][mi], aS + aRow[mi] + (ch << 4));
                }
                #pragma unroll
                for (int nj = 0; nj < 4; nj++) {
                    int ch = (2 * (s + 1) + cbB) ^ bR7[nj];
                    ldmx4(bfr[cur ^ 1][nj], bS + bRow[nj] + (ch << 4));
                }
            }
            #pragma unroll
            for (int mi = 0; mi < 4; mi++)
                #pragma unroll
                for (int ni = 0; ni < 8; ni++)
                    mma_f16(acc[mi][ni], afr[cur][mi],
                            bfr[cur][ni >> 1][(ni & 1) * 2],
                            bfr[cur][ni >> 1][(ni & 1) * 2 + 1]);
        }
    }

    // ---- epilogue: direct STG.64 ----
    const int row0 = mt * 128 + warp_m * 64 + g;
    const int col0 = bx * 128 + warp_n * 64 + tig * 2;
    #pragma unroll
    for (int mi = 0; mi < 4; mi++) {
        #pragma unroll
        for (int ni = 0; ni < 8; ni++) {
            float* p0 = out + (size_t)(row0 + mi * 16) * N_TOT + col0 + ni * 8;
            *(float2*)p0               = make_float2(acc[mi][ni][0], acc[mi][ni][1]);
            *(float2*)(p0 + 8 * N_TOT) = make_float2(acc[mi][ni][2], acc[mi][ni][3]);
        }
    }
}

// ---------------------------------------------------------------------------
extern "C" void kernel_launch(void* const* d_in, const int* in_sizes, int n_in,
                              void* d_out, int out_size) {
    (void)in_sizes; (void)n_in; (void)out_size;
    const float* X = (const float*)d_in[0];   // (1,131072,1024) f32
    const float* W = (const float*)d_in[2];   // (1024,4096) f32
    float* out = (float*)d_out;               // (1,32768,1024) f32

    cudaFuncSetAttribute(merger_gemm_kernel,
                         cudaFuncAttributeMaxDynamicSharedMemorySize, SMEM_BYTES);

    prep_w_kernel<<<(N_TOT * K_TOT / 4 + 255) / 256, 256>>>(W);
    prep_x_kernel<<<8192, 256>>>(X);
    merger_gemm_kernel<<<dim3(8, 256, 1), THREADS, SMEM_BYTES>>>(out);
}

// round 14
// speedup vs baseline: 1.0633x; 1.0633x over previous
#include <cuda_runtime.h>
#include <cuda_fp16.h>
#include <cstdint>

// ---------------------------------------------------------------------------
// LinearPatchMerger (GB300, family-safe):
//   prep_w: g_Wh[1024][4096] = fp16( column-permuted W )      (input-indexed)
//   prep_x: g_Xh[32768][4096] = fp16( unfold-permuted image_features )
//   gemm  : out = g_Xh @ g_Wh^T  via mma.m16n8k16.f16 (f32 accum)
//           128 thr/CTA, 128x128 tile, warp tile 64x64, 2 CTAs/SM,
//           B fragments double-buffered; producer deferred past slice 0.
// ---------------------------------------------------------------------------

constexpr int K_TOT = 4096;
constexpr int N_TOT = 1024;
constexpr int M_TOT = 32768;

constexpr int KC = 64;               // K halves per stage (128 B rows)
constexpr int NCHUNK = K_TOT / KC;   // 64
constexpr int NSTAGE = 3;
constexpr int THREADS = 128;         // 4 warps, 2x2 of 64x64 warp tiles

constexpr int A_BYTES = 128 * KC * 2;        // 16 KB
constexpr int B_BYTES = 128 * KC * 2;        // 16 KB
constexpr int STAGE   = A_BYTES + B_BYTES;   // 32 KB
constexpr int SMEM_BYTES = NSTAGE * STAGE;   // 96 KB

__device__ __half g_Xh[(size_t)M_TOT * K_TOT];  // 268 MB permuted fp16 A
__device__ __half g_Wh[(size_t)N_TOT * K_TOT];  // 8 MB permuted fp16 W

#define DEV __device__ __forceinline__

DEV uint32_t smem_u32(const void* p) {
    uint32_t a;
    asm("{ .reg .u64 t; cvta.to.shared.u64 t, %1; cvt.u32.u64 %0, t; }"
        : "=r"(a) : "l"(p));
    return a;
}
DEV void cp16(uint32_t dst, const void* src) {
    asm volatile("cp.async.ca.shared.global [%0], [%1], 16;"
                 :: "r"(dst), "l"(src) : "memory");
}
DEV void cp_commit() { asm volatile("cp.async.commit_group;" ::: "memory"); }
template <int N> DEV void cp_wait() {
    asm volatile("cp.async.wait_group %0;" :: "n"(N) : "memory");
}
DEV void ldmx4(uint32_t* r, uint32_t a) {
    asm volatile("ldmatrix.sync.aligned.m8n8.x4.shared.b16 {%0,%1,%2,%3}, [%4];"
                 : "=r"(r[0]), "=r"(r[1]), "=r"(r[2]), "=r"(r[3]) : "r"(a));
}
DEV void mma_f16(float* d, const uint32_t* a, uint32_t b0, uint32_t b1) {
    asm volatile(
        "mma.sync.aligned.m16n8k16.row.col.f32.f16.f16.f32 "
        "{%0,%1,%2,%3}, {%4,%5,%6,%7}, {%8,%9}, {%0,%1,%2,%3};"
        : "+f"(d[0]), "+f"(d[1]), "+f"(d[2]), "+f"(d[3])
        : "r"(a[0]), "r"(a[1]), "r"(a[2]), "r"(a[3]), "r"(b0), "r"(b1));
}

// ---------------------------------------------------------------------------
// prep W (input-indexed, coalesced both sides)
// ---------------------------------------------------------------------------
__global__ void prep_w_kernel(const float* __restrict__ W) {
    int o = blockIdx.x * blockDim.x + threadIdx.x;   // 0 .. 1M-1
    if (o >= N_TOT * K_TOT / 4) return;
    int dout = o >> 10;
    int d    = o & 1023;
    float4 v = ((const float4*)W)[o];
    __half* base = g_Wh + ((size_t)dout << 12) + d;
    base[0]    = __float2half_rn(v.x);
    base[1024] = __float2half_rn(v.y);
    base[2048] = __float2half_rn(v.z);
    base[3072] = __float2half_rn(v.w);
}

// ---------------------------------------------------------------------------
// prep X: g_Xh[n][q*1024+d] = fp16( X[srcrow(n,q)][d] ), nc loads, 16B stores
// ---------------------------------------------------------------------------
__global__ void prep_x_kernel(const float* __restrict__ X) {
    const int total = M_TOT * (K_TOT / 8);
    int stride = gridDim.x * blockDim.x;
    for (int o = blockIdx.x * blockDim.x + threadIdx.x; o < total; o += stride) {
        int n  = o >> 9;
        int rh = (o & 511) << 3;
        int q  = rh >> 10;
        int d0 = rh & 1023;
        int im = n >> 12, ml = n & 4095;
        int i = ml >> 6, j = ml & 63;
        int src = (im << 14) + (((i << 1) + (q >> 1)) << 7) + (j << 1) + (q & 1);
        const float4* p = (const float4*)(X + ((size_t)src << 10) + d0);
        float4 v0 = __ldg(p);
        float4 v1 = __ldg(p + 1);
        __half2 h[4] = {
            __floats2half2_rn(v0.x, v0.y), __floats2half2_rn(v0.z, v0.w),
            __floats2half2_rn(v1.x, v1.y), __floats2half2_rn(v1.z, v1.w)};
        *(uint4*)(g_Xh + ((size_t)o << 3)) = *(const uint4*)h;
    }
}

// ---------------------------------------------------------------------------
// GEMM: grid (8 n-tiles, 256 m-tiles), 128 threads, warp tile 64x64.
// smem rows = 64 halves (128 B), 16B-chunk swizzle c^(r&7).
// Producer (cp.async for ktile kc+2) issues AFTER slice-0 MMAs.
// ---------------------------------------------------------------------------
__global__ void __launch_bounds__(THREADS, 2)
merger_gemm_kernel(float* __restrict__ out) {
    extern __shared__ __align__(1024) char sm[];
    const uint32_t sbase = smem_u32(sm);

    const int tid = threadIdx.x;
    const int wid = tid >> 5;
    const int lid = tid & 31;
    const int bx  = blockIdx.x;     // n-tile 0..7
    const int mt  = blockIdx.y;     // m-tile 0..255

    const int warp_m = wid & 1;     // 64-row half
    const int warp_n = wid >> 1;    // 64-col half
    const int g   = lid >> 2;
    const int tig = lid & 3;

    // ---- producer slots: 8 cp16 A + 8 cp16 B per thread per stage ----
    uint32_t stsOff[8];
    const __half *srcA[8], *srcB[8];
    #pragma unroll
    for (int k2 = 0; k2 < 8; k2++) {
        int f = tid + (k2 << 7);             // 0..1023
        int r = f >> 3;                      // row 0..127
        int c = f & 7;                       // 16B chunk
        stsOff[k2] = (uint32_t)(r * 128 + ((c ^ (r & 7)) << 4));
        srcA[k2] = g_Xh + ((size_t)(mt * 128 + r) << 12) + (c << 3);
        srcB[k2] = g_Wh + ((size_t)(bx * 128 + r) << 12) + (c << 3);
    }

    // ---- consumer ldmatrix lane geometry ----
    const int rA  = (lid & 15);
    const int cbA = lid >> 4;
    const int rB  = ((lid >> 4) << 3) + (lid & 7);
    const int cbB = (lid >> 3) & 1;

    uint32_t aRow[4], bRow[4];
    int aR7[4], bR7[4];
    #pragma unroll
    for (int mi = 0; mi < 4; mi++) {
        int row = warp_m * 64 + mi * 16 + rA;
        aRow[mi] = (uint32_t)(row * 128);
        aR7[mi]  = row & 7;
    }
    #pragma unroll
    for (int nj = 0; nj < 4; nj++) {
        int row = warp_n * 64 + nj * 16 + rB;
        bRow[nj] = (uint32_t)(row * 128);
        bR7[nj]  = row & 7;
    }

    float acc[4][8][4];
    #pragma unroll
    for (int mi = 0; mi < 4; mi++)
        #pragma unroll
        for (int ni = 0; ni < 8; ni++)
            #pragma unroll
            for (int r = 0; r < 4; r++) acc[mi][ni][r] = 0.0f;

    auto load_stage = [&](int st, int kc) {
        const uint32_t aS = sbase + st * STAGE;
        const uint32_t bS = aS + A_BYTES;
        #pragma unroll
        for (int k2 = 0; k2 < 8; k2++) cp16(aS + stsOff[k2], srcA[k2] + kc * KC);
        #pragma unroll
        for (int k2 = 0; k2 < 8; k2++) cp16(bS + stsOff[k2], srcB[k2] + kc * KC);
    };

    #pragma unroll
    for (int s = 0; s < NSTAGE - 1; s++) { load_stage(s, s); cp_commit(); }
    int kc_load = NSTAGE - 1;

    for (int kc = 0; kc < NCHUNK; kc++) {
        cp_wait<NSTAGE - 2>();
        __syncthreads();

        const uint32_t aS = sbase + (kc % NSTAGE) * STAGE;
        const uint32_t bS = aS + A_BYTES;

        // ---- B fragments double-buffered across the 4 k-slices ----
        uint32_t bfr[2][4][4];
        #pragma unroll
        for (int nj = 0; nj < 4; nj++) {
            int ch = cbB ^ bR7[nj];                       // s = 0
            ldmx4(bfr[0][nj], bS + bRow[nj] + (ch << 4));
        }

        #pragma unroll
        for (int s = 0; s < 4; s++) {
            const int cur = s & 1;

            uint32_t afr[4][4];
            #pragma unroll
            for (int mi = 0; mi < 4; mi++) {
                int ch = (2 * s + cbA) ^ aR7[mi];
                ldmx4(afr[mi], aS + aRow[mi] + (ch << 4));
            }
            if (s < 3) {
                #pragma unroll
                for (int nj = 0; nj < 4; nj++) {
                    int ch = (2 * (s + 1) + cbB) ^ bR7[nj];
                    ldmx4(bfr[cur ^ 1][nj], bS + bRow[nj] + (ch << 4));
                }
            }
            #pragma unroll
            for (int mi = 0; mi < 4; mi++)
                #pragma unroll
                for (int ni = 0; ni < 8; ni++)
                    mma_f16(acc[mi][ni], afr[mi],
                            bfr[cur][ni >> 1][(ni & 1) * 2],
                            bfr[cur][ni >> 1][(ni & 1) * 2 + 1]);

            // ---- deferred producer: issue cp.async AFTER slice 0's MMAs ----
            if (s == 0) {
                if (kc_load < NCHUNK) {
                    load_stage(kc_load % NSTAGE, kc_load);
                    kc_load++;
                }
                cp_commit();
            }
        }
    }

    // ---- epilogue: direct STG.64 ----
    const int row0 = mt * 128 + warp_m * 64 + g;
    const int col0 = bx * 128 + warp_n * 64 + tig * 2;
    #pragma unroll
    for (int mi = 0; mi < 4; mi++) {
        #pragma unroll
        for (int ni = 0; ni < 8; ni++) {
            float* p0 = out + (size_t)(row0 + mi * 16) * N_TOT + col0 + ni * 8;
            *(float2*)p0               = make_float2(acc[mi][ni][0], acc[mi][ni][1]);
            *(float2*)(p0 + 8 * N_TOT) = make_float2(acc[mi][ni][2], acc[mi][ni][3]);
        }
    }
}

// ---------------------------------------------------------------------------
extern "C" void kernel_launch(void* const* d_in, const int* in_sizes, int n_in,
                              void* d_out, int out_size) {
    (void)in_sizes; (void)n_in; (void)out_size;
    const float* X = (const float*)d_in[0];   // (1,131072,1024) f32
    const float* W = (const float*)d_in[2];   // (1024,4096) f32
    float* out = (float*)d_out;               // (1,32768,1024) f32

    cudaFuncSetAttribute(merger_gemm_kernel,
                         cudaFuncAttributeMaxDynamicSharedMemorySize, SMEM_BYTES);

    prep_w_kernel<<<(N_TOT * K_TOT / 4 + 255) / 256, 256>>>(W);
    prep_x_kernel<<<8192, 256>>>(X);
    merger_gemm_kernel<<<dim3(8, 256, 1), THREADS, SMEM_BYTES>>>(out);
}